// round 6
// baseline (speedup 1.0000x reference)
#include <cuda_runtime.h>

#define Nn 128
#define Tn 2048
#define Bn 64

// Precomputed exp-domain constants (written by prep_kernel each launch).
__device__ __align__(16) float g_ET[Nn * Nn];   // ET[j*N + i] = forbidden ? 0 : exp(trans[i][j])
__device__ float g_stexp[Nn];                   // exp(start) or 0
__device__ float g_enexp[Nn];                   // exp(end) or 0

__global__ void prep_kernel(const float* __restrict__ trans,
                            const float* __restrict__ st,
                            const float* __restrict__ en,
                            const int* __restrict__ ftr,
                            const int* __restrict__ fst,
                            const int* __restrict__ fen)
{
    int idx = blockIdx.x * blockDim.x + threadIdx.x;
    if (idx < Nn * Nn) {
        int j = idx >> 7;
        int i = idx & (Nn - 1);
        g_ET[idx] = ftr[i * Nn + j] ? 0.0f : expf(trans[i * Nn + j]);
    }
    if (idx < Nn) {
        g_stexp[idx] = fst[idx] ? 0.0f : expf(st[idx]);
        g_enexp[idx] = fen[idx] ? 0.0f : expf(en[idx]);
    }
}

// Packed fp32x2 ops (Blackwell): 2 fp32 FMAs/ADDs per instruction on the fma pipe.
__device__ __forceinline__ unsigned long long ffma2(unsigned long long a,
                                                    unsigned long long b,
                                                    unsigned long long c)
{
    unsigned long long d;
    asm("fma.rn.f32x2 %0, %1, %2, %3;" : "=l"(d) : "l"(a), "l"(b), "l"(c));
    return d;
}

__device__ __forceinline__ unsigned long long addf2(unsigned long long a,
                                                    unsigned long long b)
{
    unsigned long long d;
    asm("add.rn.f32x2 %0, %1, %2;" : "=l"(d) : "l"(a), "l"(b));
    return d;
}

__device__ __forceinline__ float unpack_add(unsigned long long a)
{
    float lo, hi;
    asm("mov.b64 {%0, %1}, %2;" : "=f"(lo), "=f"(hi) : "l"(a));
    return lo + hi;
}

// One dual-channel CRF step. Thread j computes output state j for BOTH channels:
// A = supervised (target-masked emissions), B = full partition.
// MODE: 0 = plain, 1 = apply pending renorm scales, 2 = compute new block maxes.
#define STEP(TSTEP, EMV, TGV, RB, WB, MODE)                                        \
    {                                                                              \
        const float emc = EMV;                                                     \
        const int tgc = TGV;                                                       \
        const int tp = (TSTEP) + 4;                                                \
        if (tp < Tn) { EMV = emrow[tp * Nn]; TGV = tgrow[tp * Nn]; }               \
        const float pB = __expf(emc);                                              \
        const float pA = (tgc != 0) ? pB : 0.0f;                                   \
        const ulonglong2* uvA = (const ulonglong2*)UA[RB];                         \
        const ulonglong2* uvB = (const ulonglong2*)UB[RB];                         \
        unsigned long long a0 = 0ull, a1 = 0ull, a2 = 0ull, a3 = 0ull;             \
        unsigned long long b0 = 0ull, b1 = 0ull, b2 = 0ull, b3 = 0ull;             \
        _Pragma("unroll")                                                          \
        for (int k = 0; k < 32; k += 2) {                                          \
            ulonglong2 uA = uvA[k];                                                \
            ulonglong2 uB = uvB[k];                                                \
            a0 = ffma2(Ep[k].x, uA.x, a0);                                         \
            a1 = ffma2(Ep[k].y, uA.y, a1);                                         \
            b0 = ffma2(Ep[k].x, uB.x, b0);                                         \
            b1 = ffma2(Ep[k].y, uB.y, b1);                                         \
            ulonglong2 uA2 = uvA[k + 1];                                           \
            ulonglong2 uB2 = uvB[k + 1];                                           \
            a2 = ffma2(Ep[k + 1].x, uA2.x, a2);                                    \
            a3 = ffma2(Ep[k + 1].y, uA2.y, a3);                                    \
            b2 = ffma2(Ep[k + 1].x, uB2.x, b2);                                    \
            b3 = ffma2(Ep[k + 1].y, uB2.y, b3);                                    \
        }                                                                          \
        float sA = unpack_add(addf2(addf2(a0, a1), addf2(a2, a3)));                \
        float sB = unpack_add(addf2(addf2(b0, b1), addf2(b2, b3)));                \
        if ((MODE) == 1) {                                                         \
            vA = sA * pA * invA; vB = sB * pB * invB;                              \
            SexpA += epA; SexpB += epB;                                            \
        } else {                                                                   \
            vA = sA * pA; vB = sB * pB;                                            \
        }                                                                          \
        UA[WB][j] = vA;                                                            \
        UB[WB][j] = vB;                                                            \
        if ((MODE) == 2) {                                                         \
            unsigned int wmA = __reduce_max_sync(0xffffffffu, __float_as_uint(vA));\
            unsigned int wmB = __reduce_max_sync(0xffffffffu, __float_as_uint(vB));\
            if (lane == 0) { wmaxA[warp] = wmA; wmaxB[warp] = wmB; }               \
        }                                                                          \
        __syncthreads();                                                           \
        if ((MODE) == 2) {                                                         \
            unsigned int rA = max(max(wmaxA[0], wmaxA[1]), max(wmaxA[2], wmaxA[3]));\
            unsigned int rB = max(max(wmaxB[0], wmaxB[1]), max(wmaxB[2], wmaxB[3]));\
            epA = (int)(rA >> 23) - 127;                                           \
            epB = (int)(rB >> 23) - 127;                                           \
            invA = __int_as_float((127 - epA) << 23);                              \
            invB = __int_as_float((127 - epB) << 23);                              \
        }                                                                          \
        if ((TSTEP) == Lm1) goto finalize;                                         \
    }

__global__ void __launch_bounds__(128, 1)
crf_kernel(const float* __restrict__ em,
           const int* __restrict__ mask,
           const int* __restrict__ tgt,
           float* __restrict__ out)
{
    __shared__ __align__(16) float UA[2][Nn];  // supervised channel alpha (scaled exp)
    __shared__ __align__(16) float UB[2][Nn];  // partition channel alpha
    __shared__ unsigned int wmaxA[4], wmaxB[4];
    __shared__ float zpA[4], zpB[4];
    __shared__ int s_len;

    const int tid = threadIdx.x;
    const int b = blockIdx.x;           // 64 blocks: one batch element, both channels
    const int j = tid;                  // output state column
    const int warp = tid >> 5;
    const int lane = tid & 31;

    // ---- sequence length from mask (int32 bools) ----
    if (tid == 0) s_len = 0;
    __syncthreads();
    {
        int cnt = 0;
        const int* mrow = mask + b * Tn;
        for (int k = tid; k < Tn; k += 128) cnt += (mrow[k] != 0) ? 1 : 0;
        #pragma unroll
        for (int o = 16; o; o >>= 1) cnt += __shfl_xor_sync(0xffffffffu, cnt, o);
        if (lane == 0) atomicAdd(&s_len, cnt);
    }

    // ---- this thread's full column of E (64 packed pairs), shared by both channels ----
    ulonglong2 Ep[32];
    {
        const ulonglong2* ecol = (const ulonglong2*)(g_ET + j * Nn);
        #pragma unroll
        for (int k = 0; k < 32; k++) Ep[k] = ecol[k];
    }
    const float enj = g_enexp[j];
    const float stj = g_stexp[j];

    const float* emrow = em + (b * Tn) * Nn + j;
    const int*   tgrow = tgt + (b * Tn) * Nn + j;

    __syncthreads();
    int L = s_len;
    int Lm1 = L - 1;
    if (Lm1 < 0) Lm1 = 0;
    if (Lm1 > Tn - 1) Lm1 = Tn - 1;

    float vA, vB;
    int SexpA = 0, SexpB = 0;
    int epA = 0, epB = 0;
    float invA = 1.0f, invB = 1.0f;

    // ---- t = 0: alpha0 = emissions(0) + start; write U[0]; first block maxes ----
    {
        float em0v = emrow[0];
        int tg0v = tgrow[0];
        float pB = __expf(em0v);
        float pA = (tg0v != 0) ? pB : 0.0f;
        vA = pA * stj;
        vB = pB * stj;
        UA[0][j] = vA;
        UB[0][j] = vB;
        unsigned int wmA = __reduce_max_sync(0xffffffffu, __float_as_uint(vA));
        unsigned int wmB = __reduce_max_sync(0xffffffffu, __float_as_uint(vB));
        if (lane == 0) { wmaxA[warp] = wmA; wmaxB[warp] = wmB; }
        __syncthreads();
        unsigned int rA = max(max(wmaxA[0], wmaxA[1]), max(wmaxA[2], wmaxA[3]));
        unsigned int rB = max(max(wmaxB[0], wmaxB[1]), max(wmaxB[2], wmaxB[3]));
        epA = (int)(rA >> 23) - 127;
        epB = (int)(rB >> 23) - 127;
        invA = __int_as_float((127 - epA) << 23);
        invB = __int_as_float((127 - epB) << 23);
    }
    if (Lm1 == 0) goto finalize;

    // ---- main scan: 4-step unroll, renorm once per 4 steps (lag-1 apply) ----
    {
        float em0, em1, em2, em3;
        int tg0, tg1, tg2, tg3;
        em0 = emrow[1 * Nn]; tg0 = tgrow[1 * Nn];
        em1 = emrow[2 * Nn]; tg1 = tgrow[2 * Nn];
        em2 = emrow[3 * Nn]; tg2 = tgrow[3 * Nn];
        em3 = emrow[4 * Nn]; tg3 = tgrow[4 * Nn];

        for (int base = 1; base < Tn; base += 4) {
            STEP(base + 0, em0, tg0, 0, 1, 1)
            STEP(base + 1, em1, tg1, 1, 0, 0)
            STEP(base + 2, em2, tg2, 0, 1, 0)
            STEP(base + 3, em3, tg3, 1, 0, 2)
        }
    }

finalize:
    // z_c = Sexp_c*ln2 + log(sum_j v_j * exp(end_j));  loss = z_B - z_A
    {
        float cA = vA * enj;
        float cB = vB * enj;
        #pragma unroll
        for (int o = 16; o; o >>= 1) {
            cA += __shfl_xor_sync(0xffffffffu, cA, o);
            cB += __shfl_xor_sync(0xffffffffu, cB, o);
        }
        if (lane == 0) { zpA[warp] = cA; zpB[warp] = cB; }
        __syncthreads();
        if (tid == 0) {
            float zsA = (zpA[0] + zpA[1]) + (zpA[2] + zpA[3]);
            float zsB = (zpB[0] + zpB[1]) + (zpB[2] + zpB[3]);
            double zA = (double)SexpA * 0.6931471805599453 + (double)logf(zsA);
            double zB = (double)SexpB * 0.6931471805599453 + (double)logf(zsB);
            out[b] = (float)(zB - zA);
        }
    }
}

#undef STEP

extern "C" void kernel_launch(void* const* d_in, const int* in_sizes, int n_in,
                              void* d_out, int out_size)
{
    const float* em    = (const float*)d_in[0];
    const int*   mask  = (const int*)d_in[1];
    const int*   tgt   = (const int*)d_in[2];
    const float* trans = (const float*)d_in[3];
    const float* st    = (const float*)d_in[4];
    const float* en    = (const float*)d_in[5];
    const int*   ftr   = (const int*)d_in[6];
    const int*   fst   = (const int*)d_in[7];
    const int*   fen   = (const int*)d_in[8];
    float* out = (float*)d_out;

    prep_kernel<<<64, 256>>>(trans, st, en, ftr, fst, fen);
    crf_kernel<<<Bn, 128>>>(em, mask, tgt, out);
}

// round 7
// speedup vs baseline: 2.0038x; 2.0038x over previous
#include <cuda_runtime.h>

#define Nn 128
#define Tn 2048
#define Bn 64

// Precomputed exp-domain constants (written by prep_kernel each launch).
__device__ __align__(16) float g_ET[Nn * Nn];  // ET[j*N+i] = forbidden ? 0 : exp(trans[i][j])  (col-major: fwd)
__device__ __align__(16) float g_E[Nn * Nn];   // E[i*N+j]  = forbidden ? 0 : exp(trans[i][j])  (row-major: bwd)
__device__ float g_stexp[Nn];                  // exp(start) or 0
__device__ float g_enexp[Nn];                  // exp(end) or 0

// Split-scan scratch (one vector + exponent per (seq-channel, direction)).
__device__ __align__(16) float g_alpha[2 * Bn][Nn];
__device__ __align__(16) float g_wvec[2 * Bn][Nn];
__device__ int g_sexpF[2 * Bn];
__device__ int g_sexpB[2 * Bn];

__global__ void prep_kernel(const float* __restrict__ trans,
                            const float* __restrict__ st,
                            const float* __restrict__ en,
                            const int* __restrict__ ftr,
                            const int* __restrict__ fst,
                            const int* __restrict__ fen)
{
    int idx = blockIdx.x * blockDim.x + threadIdx.x;
    if (idx < Nn * Nn) {
        int i = idx >> 7;          // source state
        int j = idx & (Nn - 1);    // dest state
        float x = ftr[idx] ? 0.0f : expf(trans[idx]);
        g_E[idx] = x;              // row-major
        g_ET[j * Nn + i] = x;      // col-major
    }
    if (idx < Nn) {
        g_stexp[idx] = fst[idx] ? 0.0f : expf(st[idx]);
        g_enexp[idx] = fen[idx] ? 0.0f : expf(en[idx]);
    }
}

// Packed fp32x2 ops (Blackwell): 2 fp32 FMAs/ADDs per instruction on the fma pipe.
__device__ __forceinline__ unsigned long long ffma2(unsigned long long a,
                                                    unsigned long long b,
                                                    unsigned long long c)
{
    unsigned long long d;
    asm("fma.rn.f32x2 %0, %1, %2, %3;" : "=l"(d) : "l"(a), "l"(b), "l"(c));
    return d;
}

__device__ __forceinline__ unsigned long long addf2(unsigned long long a,
                                                    unsigned long long b)
{
    unsigned long long d;
    asm("add.rn.f32x2 %0, %1, %2;" : "=l"(d) : "l"(a), "l"(b));
    return d;
}

__device__ __forceinline__ float unpack_add(unsigned long long a)
{
    float lo, hi;
    asm("mov.b64 {%0, %1}, %2;" : "=f"(lo), "=f"(hi) : "l"(a));
    return lo + hi;
}

// 128-dim dot product: this thread's E row/column (regs) x broadcast vector (smem).
__device__ __forceinline__ float matvec128(const float* __restrict__ Ub,
                                           const ulonglong2* __restrict__ Ep)
{
    const ulonglong2* uvec = (const ulonglong2*)Ub;
    unsigned long long a0 = 0ull, a1 = 0ull, a2 = 0ull, a3 = 0ull;
    unsigned long long a4 = 0ull, a5 = 0ull, a6 = 0ull, a7 = 0ull;
    #pragma unroll
    for (int k = 0; k < 32; k += 4) {
        ulonglong2 u0 = uvec[k];
        ulonglong2 u1 = uvec[k + 1];
        ulonglong2 u2 = uvec[k + 2];
        ulonglong2 u3 = uvec[k + 3];
        a0 = ffma2(Ep[k].x,     u0.x, a0);
        a1 = ffma2(Ep[k].y,     u0.y, a1);
        a2 = ffma2(Ep[k + 1].x, u1.x, a2);
        a3 = ffma2(Ep[k + 1].y, u1.y, a3);
        a4 = ffma2(Ep[k + 2].x, u2.x, a4);
        a5 = ffma2(Ep[k + 2].y, u2.y, a5);
        a6 = ffma2(Ep[k + 3].x, u3.x, a6);
        a7 = ffma2(Ep[k + 3].y, u3.y, a7);
    }
    a0 = addf2(a0, a1); a2 = addf2(a2, a3);
    a4 = addf2(a4, a5); a6 = addf2(a6, a7);
    a0 = addf2(a0, a2); a4 = addf2(a4, a6);
    a0 = addf2(a0, a4);
    return unpack_add(a0);
}

// Forward step (alpha_t from alpha_{t-1}). MODE: 0 plain, 1 apply pending scale, 2 compute max.
#define FSTEP(TSTEP, EMV, TGV, RB, WB, MODE)                                    \
    {                                                                           \
        float p = __expf(EMV);                                                  \
        if (sup && (TGV) == 0) p = 0.0f;                                        \
        const int tp = (TSTEP) + 4;                                             \
        if (tp < Tn) { EMV = emrow[tp * Nn]; TGV = tgrow[tp * Nn]; }            \
        float s = matvec128(U[RB], Ep);                                         \
        if ((MODE) == 1) { v = s * p * inv_pend; Sexp += e_pend; }              \
        else             { v = s * p; }                                         \
        U[WB][j] = v;                                                           \
        if ((MODE) == 2) {                                                      \
            unsigned int wmu = __reduce_max_sync(0xffffffffu, __float_as_uint(v)); \
            if (lane == 0) wmaxbuf[warp] = wmu;                                 \
        }                                                                       \
        __syncthreads();                                                        \
        if ((MODE) == 2) {                                                      \
            unsigned int rm = max(max(wmaxbuf[0], wmaxbuf[1]),                  \
                                  max(wmaxbuf[2], wmaxbuf[3]));                 \
            e_pend = (int)(rm >> 23) - 127;                                     \
            inv_pend = __int_as_float((127 - e_pend) << 23);                    \
        }                                                                       \
        if ((TSTEP) == tendF) goto fin_f;                                       \
    }

// Backward step (w_{t-1} = E (p_t o w_t)). Produces w_{TSTEP-1} in v.
#define BSTEP(TSTEP, EMV, TGV, WB, MODE)                                        \
    {                                                                           \
        float p = __expf(EMV);                                                  \
        if (sup && (TGV) == 0) p = 0.0f;                                        \
        const int tp = (TSTEP) - 4;                                             \
        if (tp >= 0) { EMV = emrow[tp * Nn]; TGV = tgrow[tp * Nn]; }            \
        U[WB][j] = p * v;                                                       \
        __syncthreads();                                                        \
        if ((MODE) == 1) {                                                      \
            unsigned int rm = max(max(wmaxbuf[0], wmaxbuf[1]),                  \
                                  max(wmaxbuf[2], wmaxbuf[3]));                 \
            e_pend = (int)(rm >> 23) - 127;                                     \
            inv_pend = __int_as_float((127 - e_pend) << 23);                    \
            float s = matvec128(U[WB], Ep);                                     \
            v = s * inv_pend;                                                   \
            Sexp += e_pend;                                                     \
        } else {                                                                \
            v = matvec128(U[WB], Ep);                                           \
        }                                                                       \
        if ((MODE) == 2) {                                                      \
            unsigned int wmu = __reduce_max_sync(0xffffffffu, __float_as_uint(v)); \
            if (lane == 0) wmaxbuf[warp] = wmu;                                 \
        }                                                                       \
        if ((TSTEP) == m) goto fin_b;                                           \
    }

__global__ void __launch_bounds__(128, 2)
crf_scan_kernel(const float* __restrict__ em,
                const int* __restrict__ mask,
                const int* __restrict__ tgt)
{
    __shared__ __align__(16) float U[2][Nn];
    __shared__ unsigned int wmaxbuf[4];
    __shared__ int s_len;

    const int tid = threadIdx.x;
    const int bidx = blockIdx.x;        // 256 blocks: (seq-channel sc) x (dir)
    const int dir = bidx & 1;           // 0 = forward, 1 = backward
    const int sc = bidx >> 1;           // (b<<1) | c
    const int c = sc & 1;               // 0 = supervised, 1 = partition
    const int b = sc >> 1;
    const int j = tid;
    const int warp = tid >> 5;
    const int lane = tid & 31;
    const bool sup = (c == 0);

    // ---- sequence length from mask (int32 bools) ----
    if (tid == 0) s_len = 0;
    __syncthreads();
    {
        int cnt = 0;
        const int* mrow = mask + b * Tn;
        for (int k = tid; k < Tn; k += 128) cnt += (mrow[k] != 0) ? 1 : 0;
        #pragma unroll
        for (int o = 16; o; o >>= 1) cnt += __shfl_xor_sync(0xffffffffu, cnt, o);
        if (lane == 0) atomicAdd(&s_len, cnt);
    }

    // ---- E operand: forward uses column j of exp(trans) (g_ET), backward row j (g_E).
    // Both are contiguous 128-float runs at offset j*Nn.
    ulonglong2 Ep[32];
    {
        const float* Emat = (dir == 0) ? g_ET : g_E;
        const ulonglong2* erow = (const ulonglong2*)(Emat + j * Nn);
        #pragma unroll
        for (int k = 0; k < 32; k++) Ep[k] = erow[k];
    }
    const float enj = g_enexp[j];
    const float stj = g_stexp[j];

    const float* emrow = em + (b * Tn) * Nn + j;
    const int*   tgrow = tgt + (b * Tn) * Nn + j;

    __syncthreads();
    int L = s_len;
    if (L < 1) L = 1;
    if (L > Tn) L = Tn;
    const int m = (L >> 1) > 0 ? (L >> 1) : 1;   // split point, 1 <= m <= L-1 (or m=1 when L=1)
    const int tendF = m - 1;

    float v;
    int Sexp = 0;
    int e_pend = 0;
    float inv_pend = 1.0f;

    if (dir == 0) {
        // ================= FORWARD: compute alpha_{m-1} =================
        {
            float em0v = emrow[0];
            int tg0v = tgrow[0];
            float p = __expf(em0v);
            if (sup && tg0v == 0) p = 0.0f;
            v = p * stj;
            U[0][j] = v;
            unsigned int wmu = __reduce_max_sync(0xffffffffu, __float_as_uint(v));
            if (lane == 0) wmaxbuf[warp] = wmu;
            __syncthreads();
            unsigned int rm = max(max(wmaxbuf[0], wmaxbuf[1]),
                                  max(wmaxbuf[2], wmaxbuf[3]));
            e_pend = (int)(rm >> 23) - 127;
            inv_pend = __int_as_float((127 - e_pend) << 23);
        }
        if (tendF == 0) goto fin_f;
        {
            float em0, em1, em2, em3;
            int tg0, tg1, tg2, tg3;
            em0 = emrow[1 * Nn]; tg0 = tgrow[1 * Nn];
            em1 = emrow[2 * Nn]; tg1 = tgrow[2 * Nn];
            em2 = emrow[3 * Nn]; tg2 = tgrow[3 * Nn];
            em3 = emrow[4 * Nn]; tg3 = tgrow[4 * Nn];
            for (int base = 1; base < Tn; base += 4) {
                FSTEP(base + 0, em0, tg0, 0, 1, 1)
                FSTEP(base + 1, em1, tg1, 1, 0, 0)
                FSTEP(base + 2, em2, tg2, 0, 1, 0)
                FSTEP(base + 3, em3, tg3, 1, 0, 2)
            }
        }
fin_f:
        g_alpha[sc][j] = v;
        if (tid == 0) g_sexpF[sc] = Sexp;
    } else {
        // ================= BACKWARD: compute w_{m-1} =================
        // w_{L-1} = en;  w_{t-1} = E (p_t o w_t)  for t = L-1 .. m
        v = enj;
        {
            unsigned int wmu = __reduce_max_sync(0xffffffffu, __float_as_uint(v));
            if (lane == 0) wmaxbuf[warp] = wmu;   // read after first BSTEP's bar
        }
        if (L - 1 < m) goto fin_b;
        {
            const int t0i = L - 1;
            float em0, em1, em2, em3;
            int tg0, tg1, tg2, tg3;
            em0 = emrow[t0i * Nn];                          tg0 = tgrow[t0i * Nn];
            em1 = (t0i - 1 >= 0) ? emrow[(t0i - 1) * Nn] : 0.0f;
            tg1 = (t0i - 1 >= 0) ? tgrow[(t0i - 1) * Nn] : 1;
            em2 = (t0i - 2 >= 0) ? emrow[(t0i - 2) * Nn] : 0.0f;
            tg2 = (t0i - 2 >= 0) ? tgrow[(t0i - 2) * Nn] : 1;
            em3 = (t0i - 3 >= 0) ? emrow[(t0i - 3) * Nn] : 0.0f;
            tg3 = (t0i - 3 >= 0) ? tgrow[(t0i - 3) * Nn] : 1;
            for (int t0 = t0i; t0 >= 1; t0 -= 4) {
                BSTEP(t0 - 0, em0, tg0, 0, 1)
                BSTEP(t0 - 1, em1, tg1, 1, 0)
                BSTEP(t0 - 2, em2, tg2, 0, 0)
                BSTEP(t0 - 3, em3, tg3, 1, 2)
            }
        }
fin_b:
        g_wvec[sc][j] = v;
        if (tid == 0) g_sexpB[sc] = Sexp;
    }
}

#undef FSTEP
#undef BSTEP

// Combine: z_c = (SexpF+SexpB)*ln2 + log(alpha . w);  loss[b] = z_part - z_sup.
__global__ void combine_kernel(float* __restrict__ out)
{
    __shared__ float zpA[4], zpB[4];
    const int b = blockIdx.x;
    const int j = threadIdx.x;
    const int warp = j >> 5;
    const int lane = j & 31;
    const int scA = (b << 1);
    const int scB = scA | 1;

    float dA = g_alpha[scA][j] * g_wvec[scA][j];
    float dB = g_alpha[scB][j] * g_wvec[scB][j];
    #pragma unroll
    for (int o = 16; o; o >>= 1) {
        dA += __shfl_xor_sync(0xffffffffu, dA, o);
        dB += __shfl_xor_sync(0xffffffffu, dB, o);
    }
    if (lane == 0) { zpA[warp] = dA; zpB[warp] = dB; }
    __syncthreads();
    if (j == 0) {
        float sA = (zpA[0] + zpA[1]) + (zpA[2] + zpA[3]);
        float sB = (zpB[0] + zpB[1]) + (zpB[2] + zpB[3]);
        double zA = (double)(g_sexpF[scA] + g_sexpB[scA]) * 0.6931471805599453
                  + (double)logf(sA);
        double zB = (double)(g_sexpF[scB] + g_sexpB[scB]) * 0.6931471805599453
                  + (double)logf(sB);
        out[b] = (float)(zB - zA);
    }
}

extern "C" void kernel_launch(void* const* d_in, const int* in_sizes, int n_in,
                              void* d_out, int out_size)
{
    const float* em    = (const float*)d_in[0];
    const int*   mask  = (const int*)d_in[1];
    const int*   tgt   = (const int*)d_in[2];
    const float* trans = (const float*)d_in[3];
    const float* st    = (const float*)d_in[4];
    const float* en    = (const float*)d_in[5];
    const int*   ftr   = (const int*)d_in[6];
    const int*   fst   = (const int*)d_in[7];
    const int*   fen   = (const int*)d_in[8];
    float* out = (float*)d_out;

    prep_kernel<<<64, 256>>>(trans, st, en, ftr, fst, fen);
    crf_scan_kernel<<<4 * Bn, 128>>>(em, mask, tgt);
    combine_kernel<<<Bn, 128>>>(out);
}